// round 14
// baseline (speedup 1.0000x reference)
#include <cuda_runtime.h>
#include <cuda_bf16.h>
#include <cuda_fp16.h>

#define N_NODES 50000
#define E_EDGES 800000
#define D 64
#define NC 40
#define RB 128            // rows per block in GEMM kernels

typedef unsigned long long u64;

// Scratch (allocation-free rule: __device__ globals).
__device__ int g_cnt[N_NODES];                        // in-degree (excl self)
__device__ __align__(16) float  g_dinv[N_NODES];      // rsqrt(deg+1)
__device__ __align__(16) __half g_hsh[N_NODES * D];   // fp16 pre-scaled features
__device__ __align__(16) float  g_agg[N_NODES * D];   // fp32 agg (seeded with self term)

// ---- f32x2 packed helpers (FFMA2: 2 fp32 FMAs / instruction) -------------
__device__ __forceinline__ u64 pack2(float lo, float hi) {
    u64 r; asm("mov.b64 %0, {%1, %2};" : "=l"(r) : "f"(lo), "f"(hi)); return r;
}
__device__ __forceinline__ u64 dup2(float v) { return pack2(v, v); }
__device__ __forceinline__ void unpack2(u64 p, float& lo, float& hi) {
    asm("mov.b64 {%0, %1}, %2;" : "=f"(lo), "=f"(hi) : "l"(p));
}
__device__ __forceinline__ void fma2(u64& d, u64 a, u64 b) {
    asm("fma.rn.f32x2 %0, %1, %2, %0;" : "+l"(d) : "l"(a), "l"(b));
}
__device__ __forceinline__ float tanh_fast(float x) {
    float y; asm("tanh.approx.f32 %0, %1;" : "=f"(y) : "f"(x)); return y;
}

// ---------------------------------------------------------------------------
// Degree count (g_cnt zeroed by cudaMemsetAsync), then dinv = rsqrt(cnt+1)
// ---------------------------------------------------------------------------
__global__ void k_count(const int* __restrict__ dst) {
    int e = blockIdx.x * blockDim.x + threadIdx.x;
    if (e < E_EDGES) atomicAdd(&g_cnt[dst[e]], 1);
}
__global__ void k_finish_dinv() {
    int i = blockIdx.x * blockDim.x + threadIdx.x;
    if (i < N_NODES) g_dinv[i] = rsqrtf((float)(g_cnt[i] + 1));
}

// ---------------------------------------------------------------------------
// Store helper: fp32 self-loop seed into agg, fp16 copy for scatter gathers
// ---------------------------------------------------------------------------
__device__ __forceinline__ void store_scaled(int row, int c4, float4 v) {
    *reinterpret_cast<float4*>(g_agg + (size_t)row * D + c4) = v;
    __half2 h01 = __floats2half2_rn(v.x, v.y);
    __half2 h23 = __floats2half2_rn(v.z, v.w);
    uint2 packed;
    packed.x = *reinterpret_cast<unsigned*>(&h01);
    packed.y = *reinterpret_cast<unsigned*>(&h23);
    *reinterpret_cast<uint2*>(g_hsh + (size_t)row * D + c4) = packed;
}

// 8 rows x 4 cols tile MAC over one k-block of 4, using f32x2 packed FMA.
__device__ __forceinline__ void mac_k4_f32x2(const float (*sW)[D], const float (*sX)[D],
                                             int k4, int tr, int tc,
                                             u64 acc01[8], u64 acc23[8]) {
    float4 w0 = *reinterpret_cast<const float4*>(&sW[k4 * 4 + 0][tc * 4]);
    float4 w1 = *reinterpret_cast<const float4*>(&sW[k4 * 4 + 1][tc * 4]);
    float4 w2 = *reinterpret_cast<const float4*>(&sW[k4 * 4 + 2][tc * 4]);
    float4 w3 = *reinterpret_cast<const float4*>(&sW[k4 * 4 + 3][tc * 4]);
    u64 w0a = pack2(w0.x, w0.y), w0b = pack2(w0.z, w0.w);
    u64 w1a = pack2(w1.x, w1.y), w1b = pack2(w1.z, w1.w);
    u64 w2a = pack2(w2.x, w2.y), w2b = pack2(w2.z, w2.w);
    u64 w3a = pack2(w3.x, w3.y), w3b = pack2(w3.z, w3.w);
    #pragma unroll
    for (int i = 0; i < 8; i++) {
        float4 xv = *reinterpret_cast<const float4*>(&sX[tr * 8 + i][k4 * 4]);
        u64 x0 = dup2(xv.x), x1 = dup2(xv.y), x2 = dup2(xv.z), x3 = dup2(xv.w);
        fma2(acc01[i], x0, w0a); fma2(acc23[i], x0, w0b);
        fma2(acc01[i], x1, w1a); fma2(acc23[i], x1, w1b);
        fma2(acc01[i], x2, w2a); fma2(acc23[i], x2, w2b);
        fma2(acc01[i], x3, w3a); fma2(acc23[i], x3, w3b);
    }
}

// ---------------------------------------------------------------------------
// Layer-1 GEMM: hs = (x @ W1) * dinv[row]; agg = hs (fp32); hsh = hs (fp16)
// ---------------------------------------------------------------------------
__global__ void __launch_bounds__(256) k_gemm1(const float* __restrict__ x,
                                               const float* __restrict__ W1) {
    __shared__ float sW[D][D];
    __shared__ float sx[RB][D];
    int tid = threadIdx.x;
    int row0 = blockIdx.x * RB;

    #pragma unroll
    for (int i = 0; i < 4; i++) {
        int idx = tid * 4 + i * 1024;
        *reinterpret_cast<float4*>(&sW[0][0] + idx) =
            *reinterpret_cast<const float4*>(W1 + idx);
    }
    #pragma unroll
    for (int i = 0; i < 8; i++) {
        int lin = tid + i * 256;
        int r = lin >> 4;
        int c4 = (lin & 15) * 4;
        int row = row0 + r;
        float4 v = make_float4(0.f, 0.f, 0.f, 0.f);
        if (row < N_NODES) v = *reinterpret_cast<const float4*>(x + (size_t)row * D + c4);
        *reinterpret_cast<float4*>(&sx[r][c4]) = v;
    }
    __syncthreads();

    int tc = tid & 15;
    int tr = tid >> 4;
    u64 acc01[8], acc23[8];
    #pragma unroll
    for (int i = 0; i < 8; i++) { acc01[i] = 0ull; acc23[i] = 0ull; }
    #pragma unroll
    for (int k4 = 0; k4 < D / 4; k4++) mac_k4_f32x2(sW, sx, k4, tr, tc, acc01, acc23);

    #pragma unroll
    for (int i = 0; i < 8; i++) {
        int row = row0 + tr * 8 + i;
        if (row < N_NODES) {
            float di = g_dinv[row];
            float a0, a1, a2, a3;
            unpack2(acc01[i], a0, a1);
            unpack2(acc23[i], a2, a3);
            store_scaled(row, tc * 4, make_float4(a0 * di, a1 * di, a2 * di, a3 * di));
        }
    }
}

// ---------------------------------------------------------------------------
// Edge scatter: agg[dst] += hsh[src].
// 8 lanes/edge: each lane gathers 16B (8 halfs, LDG.128) and issues two
// float4 atomics. Halves L1 wavefront + index-load work vs 16 lanes/edge;
// RED count (the L2 RMW floor) unchanged.
// ---------------------------------------------------------------------------
__global__ void k_scatter(const int* __restrict__ src,
                          const int* __restrict__ dst) {
    long long idx = (long long)blockIdx.x * blockDim.x + threadIdx.x;
    int e = (int)(idx >> 3);
    int c = (int)(idx & 7);            // uint4 group: halfs c*8 .. c*8+7
    if (e >= E_EDGES) return;
    int s = src[e];
    int d = dst[e];
    uint4 p = reinterpret_cast<const uint4*>(g_hsh + (size_t)s * D)[c];
    __half2 h0 = *reinterpret_cast<__half2*>(&p.x);
    __half2 h1 = *reinterpret_cast<__half2*>(&p.y);
    __half2 h2 = *reinterpret_cast<__half2*>(&p.z);
    __half2 h3 = *reinterpret_cast<__half2*>(&p.w);
    float2 f0 = __half22float2(h0);
    float2 f1 = __half22float2(h1);
    float2 f2 = __half22float2(h2);
    float2 f3 = __half22float2(h3);
    float4* a = reinterpret_cast<float4*>(g_agg + (size_t)d * D) + c * 2;
    atomicAdd(a + 0, make_float4(f0.x, f0.y, f1.x, f1.y));
    atomicAdd(a + 1, make_float4(f2.x, f2.y, f3.x, f3.y));
}

// ---------------------------------------------------------------------------
// Fused: h1 = tanh(agg * dinv + b1); hs = (h1 @ W2) * dinv; agg/hsh = hs
// ---------------------------------------------------------------------------
__global__ void __launch_bounds__(256) k_layer2(const float* __restrict__ W2,
                                                const float* __restrict__ b1) {
    __shared__ float sW[D][D];
    __shared__ float st[RB][D];
    int tid = threadIdx.x;
    int row0 = blockIdx.x * RB;

    #pragma unroll
    for (int i = 0; i < 4; i++) {
        int idx = tid * 4 + i * 1024;
        *reinterpret_cast<float4*>(&sW[0][0] + idx) =
            *reinterpret_cast<const float4*>(W2 + idx);
    }
    #pragma unroll
    for (int i = 0; i < 8; i++) {
        int lin = tid + i * 256;
        int r = lin >> 4;
        int c4 = (lin & 15) * 4;
        int row = row0 + r;
        float4 v = make_float4(0.f, 0.f, 0.f, 0.f);
        if (row < N_NODES) {
            float di = g_dinv[row];
            float4 a = *reinterpret_cast<const float4*>(g_agg + (size_t)row * D + c4);
            float4 b = *reinterpret_cast<const float4*>(b1 + c4);
            v.x = tanh_fast(fmaf(a.x, di, b.x));
            v.y = tanh_fast(fmaf(a.y, di, b.y));
            v.z = tanh_fast(fmaf(a.z, di, b.z));
            v.w = tanh_fast(fmaf(a.w, di, b.w));
        }
        *reinterpret_cast<float4*>(&st[r][c4]) = v;
    }
    __syncthreads();

    int tc = tid & 15;
    int tr = tid >> 4;
    u64 acc01[8], acc23[8];
    #pragma unroll
    for (int i = 0; i < 8; i++) { acc01[i] = 0ull; acc23[i] = 0ull; }
    #pragma unroll
    for (int k4 = 0; k4 < D / 4; k4++) mac_k4_f32x2(sW, st, k4, tr, tc, acc01, acc23);

    #pragma unroll
    for (int i = 0; i < 8; i++) {
        int row = row0 + tr * 8 + i;
        if (row < N_NODES) {
            float di = g_dinv[row];
            float a0, a1, a2, a3;
            unpack2(acc01[i], a0, a1);
            unpack2(acc23[i], a2, a3);
            store_scaled(row, tc * 4, make_float4(a0 * di, a1 * di, a2 * di, a3 * di));
        }
    }
}

// ---------------------------------------------------------------------------
// Fused final: h = tanh(agg * dinv + b2)  -> d_out[N*NC ..]  (h output)
//              out = h @ Wc + bc          -> d_out[0 .. N*NC) (logits)
// ---------------------------------------------------------------------------
__global__ void __launch_bounds__(256) k_final(const float* __restrict__ Wc,
                                               const float* __restrict__ b2,
                                               const float* __restrict__ bc,
                                               float* __restrict__ out) {
    __shared__ float sW[D][NC];
    __shared__ float st[RB][D];
    int tid = threadIdx.x;
    int row0 = blockIdx.x * RB;

    #pragma unroll
    for (int i = 0; i < 3; i++) {
        int f4 = tid + i * 256;
        if (f4 < D * NC / 4)
            *(reinterpret_cast<float4*>(&sW[0][0]) + f4) =
                *(reinterpret_cast<const float4*>(Wc) + f4);
    }
    #pragma unroll
    for (int i = 0; i < 8; i++) {
        int lin = tid + i * 256;
        int r = lin >> 4;
        int c4 = (lin & 15) * 4;
        int row = row0 + r;
        float4 v = make_float4(0.f, 0.f, 0.f, 0.f);
        if (row < N_NODES) {
            float di = g_dinv[row];
            float4 a = *reinterpret_cast<const float4*>(g_agg + (size_t)row * D + c4);
            float4 b = *reinterpret_cast<const float4*>(b2 + c4);
            v.x = tanh_fast(fmaf(a.x, di, b.x));
            v.y = tanh_fast(fmaf(a.y, di, b.y));
            v.z = tanh_fast(fmaf(a.z, di, b.z));
            v.w = tanh_fast(fmaf(a.w, di, b.w));
            *reinterpret_cast<float4*>(out + (size_t)N_NODES * NC + (size_t)row * D + c4) = v;
        }
        *reinterpret_cast<float4*>(&st[r][c4]) = v;
    }
    __syncthreads();

    int tc = tid & 15;
    int tr = tid >> 4;
    if (tc < NC / 4) {
        float4 bcv = *reinterpret_cast<const float4*>(bc + tc * 4);
        u64 acc01[8], acc23[8];
        #pragma unroll
        for (int i = 0; i < 8; i++) {
            acc01[i] = pack2(bcv.x, bcv.y);
            acc23[i] = pack2(bcv.z, bcv.w);
        }
        #pragma unroll
        for (int k4 = 0; k4 < D / 4; k4++) {
            float4 w0 = *reinterpret_cast<float4*>(&sW[k4 * 4 + 0][tc * 4]);
            float4 w1 = *reinterpret_cast<float4*>(&sW[k4 * 4 + 1][tc * 4]);
            float4 w2 = *reinterpret_cast<float4*>(&sW[k4 * 4 + 2][tc * 4]);
            float4 w3 = *reinterpret_cast<float4*>(&sW[k4 * 4 + 3][tc * 4]);
            u64 w0a = pack2(w0.x, w0.y), w0b = pack2(w0.z, w0.w);
            u64 w1a = pack2(w1.x, w1.y), w1b = pack2(w1.z, w1.w);
            u64 w2a = pack2(w2.x, w2.y), w2b = pack2(w2.z, w2.w);
            u64 w3a = pack2(w3.x, w3.y), w3b = pack2(w3.z, w3.w);
            #pragma unroll
            for (int i = 0; i < 8; i++) {
                float4 xv = *reinterpret_cast<float4*>(&st[tr * 8 + i][k4 * 4]);
                u64 x0 = dup2(xv.x), x1 = dup2(xv.y), x2 = dup2(xv.z), x3 = dup2(xv.w);
                fma2(acc01[i], x0, w0a); fma2(acc23[i], x0, w0b);
                fma2(acc01[i], x1, w1a); fma2(acc23[i], x1, w1b);
                fma2(acc01[i], x2, w2a); fma2(acc23[i], x2, w2b);
                fma2(acc01[i], x3, w3a); fma2(acc23[i], x3, w3b);
            }
        }
        #pragma unroll
        for (int i = 0; i < 8; i++) {
            int row = row0 + tr * 8 + i;
            if (row < N_NODES) {
                float a0, a1, a2, a3;
                unpack2(acc01[i], a0, a1);
                unpack2(acc23[i], a2, a3);
                *reinterpret_cast<float4*>(out + (size_t)row * NC + tc * 4) =
                    make_float4(a0, a1, a2, a3);
            }
        }
    }
}

// ---------------------------------------------------------------------------
extern "C" void kernel_launch(void* const* d_in, const int* in_sizes, int n_in,
                              void* d_out, int out_size) {
    const float* x   = (const float*)d_in[0];
    const int*   ei  = (const int*)d_in[1];   // [2, E] int32 (JAX x64 disabled)
    const float* W1  = (const float*)d_in[2];
    const float* b1  = (const float*)d_in[3];
    const float* W2  = (const float*)d_in[4];
    const float* b2  = (const float*)d_in[5];
    const float* Wc  = (const float*)d_in[6];
    const float* bc  = (const float*)d_in[7];
    float* out = (float*)d_out;

    const int* src = ei;              // edge_index[0]
    const int* dst = ei + E_EDGES;    // edge_index[1]

    const int TB = 256;
    const int gN    = (N_NODES + TB - 1) / TB;
    const int gE    = (E_EDGES + TB - 1) / TB;
    const int gRows = (N_NODES + RB - 1) / RB;            // 391
    const long long scatterThreads = (long long)E_EDGES * 8;
    const int gScat = (int)((scatterThreads + TB - 1) / TB);

    void* cnt_ptr = nullptr;
    cudaGetSymbolAddress(&cnt_ptr, g_cnt);
    cudaMemsetAsync(cnt_ptr, 0, N_NODES * sizeof(int));
    k_count      <<<gE, TB>>>(dst);
    k_finish_dinv<<<gN, TB>>>();

    k_gemm1   <<<gRows, TB>>>(x, W1);
    k_scatter <<<gScat, TB>>>(src, dst);
    k_layer2  <<<gRows, TB>>>(W2, b1);
    k_scatter <<<gScat, TB>>>(src, dst);
    k_final   <<<gRows, TB>>>(Wc, b2, bc, out);
}

// round 15
// speedup vs baseline: 1.6301x; 1.6301x over previous
#include <cuda_runtime.h>
#include <cuda_bf16.h>
#include <cuda_fp16.h>

#define N_NODES 50000
#define E_EDGES 800000
#define D 64
#define NC 40
#define RB 128            // rows per block in GEMM kernels

typedef unsigned long long u64;

// Scratch (allocation-free rule: __device__ globals).
__device__ int g_cnt[N_NODES];                        // in-degree (excl self)
__device__ __align__(16) float  g_dinv[N_NODES];      // rsqrt(deg+1)
__device__ __align__(16) __half g_hsh [N_NODES * D];  // fp16 pre-scaled features (gather src)
__device__ __align__(16) __half g_aggh[N_NODES * D];  // fp16 accumulator (seeded with self)

// ---- f32x2 packed helpers (FFMA2: 2 fp32 FMAs / instruction) -------------
__device__ __forceinline__ u64 pack2(float lo, float hi) {
    u64 r; asm("mov.b64 %0, {%1, %2};" : "=l"(r) : "f"(lo), "f"(hi)); return r;
}
__device__ __forceinline__ u64 dup2(float v) { return pack2(v, v); }
__device__ __forceinline__ void unpack2(u64 p, float& lo, float& hi) {
    asm("mov.b64 {%0, %1}, %2;" : "=f"(lo), "=f"(hi) : "l"(p));
}
__device__ __forceinline__ void fma2(u64& d, u64 a, u64 b) {
    asm("fma.rn.f32x2 %0, %1, %2, %0;" : "+l"(d) : "l"(a), "l"(b));
}
__device__ __forceinline__ float tanh_fast(float x) {
    float y; asm("tanh.approx.f32 %0, %1;" : "=f"(y) : "f"(x)); return y;
}

// ---------------------------------------------------------------------------
// Degree count (g_cnt zeroed by cudaMemsetAsync), then dinv = rsqrt(cnt+1)
// ---------------------------------------------------------------------------
__global__ void k_count(const int* __restrict__ dst) {
    int e = blockIdx.x * blockDim.x + threadIdx.x;
    if (e < E_EDGES) atomicAdd(&g_cnt[dst[e]], 1);
}
__global__ void k_finish_dinv() {
    int i = blockIdx.x * blockDim.x + threadIdx.x;
    if (i < N_NODES) g_dinv[i] = rsqrtf((float)(g_cnt[i] + 1));
}

// ---------------------------------------------------------------------------
// Store helper: fp16 value into BOTH gather source and accumulator (self term)
// ---------------------------------------------------------------------------
__device__ __forceinline__ void store_scaled(int row, int c4, float4 v) {
    __half2 h01 = __floats2half2_rn(v.x, v.y);
    __half2 h23 = __floats2half2_rn(v.z, v.w);
    uint2 packed;
    packed.x = *reinterpret_cast<unsigned*>(&h01);
    packed.y = *reinterpret_cast<unsigned*>(&h23);
    *reinterpret_cast<uint2*>(g_hsh  + (size_t)row * D + c4) = packed;
    *reinterpret_cast<uint2*>(g_aggh + (size_t)row * D + c4) = packed;
}

// 8 rows x 4 cols tile MAC over one k-block of 4, using f32x2 packed FMA.
__device__ __forceinline__ void mac_k4_f32x2(const float (*sW)[D], const float (*sX)[D],
                                             int k4, int tr, int tc,
                                             u64 acc01[8], u64 acc23[8]) {
    float4 w0 = *reinterpret_cast<const float4*>(&sW[k4 * 4 + 0][tc * 4]);
    float4 w1 = *reinterpret_cast<const float4*>(&sW[k4 * 4 + 1][tc * 4]);
    float4 w2 = *reinterpret_cast<const float4*>(&sW[k4 * 4 + 2][tc * 4]);
    float4 w3 = *reinterpret_cast<const float4*>(&sW[k4 * 4 + 3][tc * 4]);
    u64 w0a = pack2(w0.x, w0.y), w0b = pack2(w0.z, w0.w);
    u64 w1a = pack2(w1.x, w1.y), w1b = pack2(w1.z, w1.w);
    u64 w2a = pack2(w2.x, w2.y), w2b = pack2(w2.z, w2.w);
    u64 w3a = pack2(w3.x, w3.y), w3b = pack2(w3.z, w3.w);
    #pragma unroll
    for (int i = 0; i < 8; i++) {
        float4 xv = *reinterpret_cast<const float4*>(&sX[tr * 8 + i][k4 * 4]);
        u64 x0 = dup2(xv.x), x1 = dup2(xv.y), x2 = dup2(xv.z), x3 = dup2(xv.w);
        fma2(acc01[i], x0, w0a); fma2(acc23[i], x0, w0b);
        fma2(acc01[i], x1, w1a); fma2(acc23[i], x1, w1b);
        fma2(acc01[i], x2, w2a); fma2(acc23[i], x2, w2b);
        fma2(acc01[i], x3, w3a); fma2(acc23[i], x3, w3b);
    }
}

// ---------------------------------------------------------------------------
// Layer-1 GEMM: hs = (x @ W1) * dinv[row]; hsh = aggh = hs (fp16)
// ---------------------------------------------------------------------------
__global__ void __launch_bounds__(256) k_gemm1(const float* __restrict__ x,
                                               const float* __restrict__ W1) {
    __shared__ float sW[D][D];
    __shared__ float sx[RB][D];
    int tid = threadIdx.x;
    int row0 = blockIdx.x * RB;

    #pragma unroll
    for (int i = 0; i < 4; i++) {
        int idx = tid * 4 + i * 1024;
        *reinterpret_cast<float4*>(&sW[0][0] + idx) =
            *reinterpret_cast<const float4*>(W1 + idx);
    }
    #pragma unroll
    for (int i = 0; i < 8; i++) {
        int lin = tid + i * 256;
        int r = lin >> 4;
        int c4 = (lin & 15) * 4;
        int row = row0 + r;
        float4 v = make_float4(0.f, 0.f, 0.f, 0.f);
        if (row < N_NODES) v = *reinterpret_cast<const float4*>(x + (size_t)row * D + c4);
        *reinterpret_cast<float4*>(&sx[r][c4]) = v;
    }
    __syncthreads();

    int tc = tid & 15;
    int tr = tid >> 4;
    u64 acc01[8], acc23[8];
    #pragma unroll
    for (int i = 0; i < 8; i++) { acc01[i] = 0ull; acc23[i] = 0ull; }
    #pragma unroll
    for (int k4 = 0; k4 < D / 4; k4++) mac_k4_f32x2(sW, sx, k4, tr, tc, acc01, acc23);

    #pragma unroll
    for (int i = 0; i < 8; i++) {
        int row = row0 + tr * 8 + i;
        if (row < N_NODES) {
            float di = g_dinv[row];
            float a0, a1, a2, a3;
            unpack2(acc01[i], a0, a1);
            unpack2(acc23[i], a2, a3);
            store_scaled(row, tc * 4, make_float4(a0 * di, a1 * di, a2 * di, a3 * di));
        }
    }
}

// ---------------------------------------------------------------------------
// Edge scatter: aggh[dst] += hsh[src], entirely in fp16.
// 8 lanes/edge: one LDG.128 gather + ONE red.global.add.v4.f16x2 per lane
// (8 halfs per RED lane -> 6.4M RED lanes/pass, half the LSU issue cost).
// ---------------------------------------------------------------------------
__global__ void k_scatter(const int* __restrict__ src,
                          const int* __restrict__ dst) {
    long long idx = (long long)blockIdx.x * blockDim.x + threadIdx.x;
    int e = (int)(idx >> 3);
    int c = (int)(idx & 7);            // halfs c*8 .. c*8+7
    if (e >= E_EDGES) return;
    int s = src[e];
    int d = dst[e];
    uint4 p = reinterpret_cast<const uint4*>(g_hsh + (size_t)s * D)[c];
    void* gen = g_aggh + (size_t)d * D + c * 8;
    u64 gp = (u64)__cvta_generic_to_global(gen);
    asm volatile("red.global.add.noftz.v4.f16x2 [%0], {%1, %2, %3, %4};"
                 :: "l"(gp), "r"(p.x), "r"(p.y), "r"(p.z), "r"(p.w)
                 : "memory");
}

// ---------------------------------------------------------------------------
// fp16 agg load + tanh prologue helper
// ---------------------------------------------------------------------------
__device__ __forceinline__ float4 load_agg_tanh(int row, int c4, float di,
                                                const float* __restrict__ bias) {
    uint2 pa = *reinterpret_cast<const uint2*>(g_aggh + (size_t)row * D + c4);
    __half2 a01 = *reinterpret_cast<__half2*>(&pa.x);
    __half2 a23 = *reinterpret_cast<__half2*>(&pa.y);
    float2 fa = __half22float2(a01);
    float2 fb = __half22float2(a23);
    float4 b = *reinterpret_cast<const float4*>(bias + c4);
    float4 v;
    v.x = tanh_fast(fmaf(fa.x, di, b.x));
    v.y = tanh_fast(fmaf(fa.y, di, b.y));
    v.z = tanh_fast(fmaf(fb.x, di, b.z));
    v.w = tanh_fast(fmaf(fb.y, di, b.w));
    return v;
}

// ---------------------------------------------------------------------------
// Fused: h1 = tanh(aggh * dinv + b1); hs = (h1 @ W2) * dinv; hsh/aggh = hs
// ---------------------------------------------------------------------------
__global__ void __launch_bounds__(256) k_layer2(const float* __restrict__ W2,
                                                const float* __restrict__ b1) {
    __shared__ float sW[D][D];
    __shared__ float st[RB][D];
    int tid = threadIdx.x;
    int row0 = blockIdx.x * RB;

    #pragma unroll
    for (int i = 0; i < 4; i++) {
        int idx = tid * 4 + i * 1024;
        *reinterpret_cast<float4*>(&sW[0][0] + idx) =
            *reinterpret_cast<const float4*>(W2 + idx);
    }
    #pragma unroll
    for (int i = 0; i < 8; i++) {
        int lin = tid + i * 256;
        int r = lin >> 4;
        int c4 = (lin & 15) * 4;
        int row = row0 + r;
        float4 v = make_float4(0.f, 0.f, 0.f, 0.f);
        if (row < N_NODES) v = load_agg_tanh(row, c4, g_dinv[row], b1);
        *reinterpret_cast<float4*>(&st[r][c4]) = v;
    }
    __syncthreads();

    int tc = tid & 15;
    int tr = tid >> 4;
    u64 acc01[8], acc23[8];
    #pragma unroll
    for (int i = 0; i < 8; i++) { acc01[i] = 0ull; acc23[i] = 0ull; }
    #pragma unroll
    for (int k4 = 0; k4 < D / 4; k4++) mac_k4_f32x2(sW, st, k4, tr, tc, acc01, acc23);

    #pragma unroll
    for (int i = 0; i < 8; i++) {
        int row = row0 + tr * 8 + i;
        if (row < N_NODES) {
            float di = g_dinv[row];
            float a0, a1, a2, a3;
            unpack2(acc01[i], a0, a1);
            unpack2(acc23[i], a2, a3);
            store_scaled(row, tc * 4, make_float4(a0 * di, a1 * di, a2 * di, a3 * di));
        }
    }
}

// ---------------------------------------------------------------------------
// Fused final: h = tanh(aggh * dinv + b2)  -> d_out[N*NC ..]  (h output)
//              out = h @ Wc + bc           -> d_out[0 .. N*NC) (logits)
// ---------------------------------------------------------------------------
__global__ void __launch_bounds__(256) k_final(const float* __restrict__ Wc,
                                               const float* __restrict__ b2,
                                               const float* __restrict__ bc,
                                               float* __restrict__ out) {
    __shared__ float sW[D][NC];
    __shared__ float st[RB][D];
    int tid = threadIdx.x;
    int row0 = blockIdx.x * RB;

    #pragma unroll
    for (int i = 0; i < 3; i++) {
        int f4 = tid + i * 256;
        if (f4 < D * NC / 4)
            *(reinterpret_cast<float4*>(&sW[0][0]) + f4) =
                *(reinterpret_cast<const float4*>(Wc) + f4);
    }
    #pragma unroll
    for (int i = 0; i < 8; i++) {
        int lin = tid + i * 256;
        int r = lin >> 4;
        int c4 = (lin & 15) * 4;
        int row = row0 + r;
        float4 v = make_float4(0.f, 0.f, 0.f, 0.f);
        if (row < N_NODES) {
            v = load_agg_tanh(row, c4, g_dinv[row], b2);
            *reinterpret_cast<float4*>(out + (size_t)N_NODES * NC + (size_t)row * D + c4) = v;
        }
        *reinterpret_cast<float4*>(&st[r][c4]) = v;
    }
    __syncthreads();

    int tc = tid & 15;
    int tr = tid >> 4;
    if (tc < NC / 4) {
        float4 bcv = *reinterpret_cast<const float4*>(bc + tc * 4);
        u64 acc01[8], acc23[8];
        #pragma unroll
        for (int i = 0; i < 8; i++) {
            acc01[i] = pack2(bcv.x, bcv.y);
            acc23[i] = pack2(bcv.z, bcv.w);
        }
        #pragma unroll
        for (int k4 = 0; k4 < D / 4; k4++) {
            float4 w0 = *reinterpret_cast<float4*>(&sW[k4 * 4 + 0][tc * 4]);
            float4 w1 = *reinterpret_cast<float4*>(&sW[k4 * 4 + 1][tc * 4]);
            float4 w2 = *reinterpret_cast<float4*>(&sW[k4 * 4 + 2][tc * 4]);
            float4 w3 = *reinterpret_cast<float4*>(&sW[k4 * 4 + 3][tc * 4]);
            u64 w0a = pack2(w0.x, w0.y), w0b = pack2(w0.z, w0.w);
            u64 w1a = pack2(w1.x, w1.y), w1b = pack2(w1.z, w1.w);
            u64 w2a = pack2(w2.x, w2.y), w2b = pack2(w2.z, w2.w);
            u64 w3a = pack2(w3.x, w3.y), w3b = pack2(w3.z, w3.w);
            #pragma unroll
            for (int i = 0; i < 8; i++) {
                float4 xv = *reinterpret_cast<float4*>(&st[tr * 8 + i][k4 * 4]);
                u64 x0 = dup2(xv.x), x1 = dup2(xv.y), x2 = dup2(xv.z), x3 = dup2(xv.w);
                fma2(acc01[i], x0, w0a); fma2(acc23[i], x0, w0b);
                fma2(acc01[i], x1, w1a); fma2(acc23[i], x1, w1b);
                fma2(acc01[i], x2, w2a); fma2(acc23[i], x2, w2b);
                fma2(acc01[i], x3, w3a); fma2(acc23[i], x3, w3b);
            }
        }
        #pragma unroll
        for (int i = 0; i < 8; i++) {
            int row = row0 + tr * 8 + i;
            if (row < N_NODES) {
                float a0, a1, a2, a3;
                unpack2(acc01[i], a0, a1);
                unpack2(acc23[i], a2, a3);
                *reinterpret_cast<float4*>(out + (size_t)row * NC + tc * 4) =
                    make_float4(a0, a1, a2, a3);
            }
        }
    }
}

// ---------------------------------------------------------------------------
extern "C" void kernel_launch(void* const* d_in, const int* in_sizes, int n_in,
                              void* d_out, int out_size) {
    const float* x   = (const float*)d_in[0];
    const int*   ei  = (const int*)d_in[1];   // [2, E] int32 (JAX x64 disabled)
    const float* W1  = (const float*)d_in[2];
    const float* b1  = (const float*)d_in[3];
    const float* W2  = (const float*)d_in[4];
    const float* b2  = (const float*)d_in[5];
    const float* Wc  = (const float*)d_in[6];
    const float* bc  = (const float*)d_in[7];
    float* out = (float*)d_out;

    const int* src = ei;              // edge_index[0]
    const int* dst = ei + E_EDGES;    // edge_index[1]

    const int TB = 256;
    const int gN    = (N_NODES + TB - 1) / TB;
    const int gE    = (E_EDGES + TB - 1) / TB;
    const int gRows = (N_NODES + RB - 1) / RB;            // 391
    const long long scatterThreads = (long long)E_EDGES * 8;
    const int gScat = (int)((scatterThreads + TB - 1) / TB);

    void* cnt_ptr = nullptr;
    cudaGetSymbolAddress(&cnt_ptr, g_cnt);
    cudaMemsetAsync(cnt_ptr, 0, N_NODES * sizeof(int));
    k_count      <<<gE, TB>>>(dst);
    k_finish_dinv<<<gN, TB>>>();

    k_gemm1   <<<gRows, TB>>>(x, W1);
    k_scatter <<<gScat, TB>>>(src, dst);
    k_layer2  <<<gRows, TB>>>(W2, b1);
    k_scatter <<<gScat, TB>>>(src, dst);
    k_final   <<<gRows, TB>>>(Wc, b2, bc, out);
}